// round 10
// baseline (speedup 1.0000x reference)
#include <cuda_runtime.h>
#include <cuda_bf16.h>
#include <cstdint>

#define BB 32
#define CC 5
#define HH 50
#define SS 20
#define EE 300
#define KK 20
#define F4N 75
#define NCS 100
#define THREADS 224
#define NGRP2 50             // 2-row groups
#define ROWOFF 40            // floats: row1 offset within group (10 float4)
#define GRPSTRIDE 100        // 100 mod 32 = 4 -> conflict-free phase banks
#define NCHUNK 8
#define NROWS_CDD (BB * CC * SS)     // 3200
#define NROWS_HIS (BB * HH * SS)     // 32000
#define NROWS_ALL (NROWS_CDD + NROWS_HIS)

#define NC_STD  (-72.134752f)
#define NC_LAST (-721347.52f)

__device__ __constant__ int c_f4cnt[NCHUNK] = {10, 10, 10, 10, 10, 10, 10, 5};
__device__ __constant__ int c_f4off[NCHUNK] = {0, 10, 20, 30, 40, 50, 60, 70};

struct Smem {
    float hisT[EE * SS];                // 24000B
    float cddc[NGRP2 * GRPSTRIDE];      // 20000B
    float simbuf[NCS * SS];             // 8000B
    float padh[SS];
    float padc[NCS];
    float wv[KK];
    float cont[THREADS];
};

__device__ float g_cddN[NROWS_CDD * EE];
__device__ float g_hisN[NROWS_HIS * EE];
__device__ float g_partial[BB * HH * CC];
__device__ unsigned int g_done;

__device__ __forceinline__ float ex2_approx(float x) {
    float r;
    asm("ex2.approx.ftz.f32 %0, %1;" : "=f"(r) : "f"(x));
    return r;
}
__device__ __forceinline__ void fma2(unsigned long long& acc,
                                     unsigned long long a, unsigned long long b) {
    asm("fma.rn.f32x2 %0, %1, %2, %0;" : "+l"(acc) : "l"(a), "l"(b));
}
__device__ __forceinline__ unsigned long long dupf(float x) {
    unsigned long long r;
    asm("mov.b64 %0, {%1, %1};" : "=l"(r) : "f"(x));
    return r;
}

// ---------------- prep: L2-normalize embedding rows into dense scratch ----------------
__global__ __launch_bounds__(256)
void knrm_prep(const int* __restrict__ cand, const int* __restrict__ clk,
               const float* __restrict__ emb)
{
    const int wid = threadIdx.x >> 5, lane = threadIdx.x & 31;
    const int row = blockIdx.x * 8 + wid;
    if (row >= NROWS_ALL) return;
    int tok;
    float* dst;
    if (row < NROWS_CDD) { tok = cand[row];             dst = g_cddN + (size_t)row * EE; }
    else                 { tok = clk[row - NROWS_CDD];  dst = g_hisN + (size_t)(row - NROWS_CDD) * EE; }
    const float* src = emb + (size_t)tok * EE;

    float4 v[3];
    float ss = 0.f;
    #pragma unroll
    for (int i = 0; i < 3; ++i) {
        int f = lane + i * 32;
        if (f < F4N) {
            v[i] = *reinterpret_cast<const float4*>(src + f * 4);
            ss = fmaf(v[i].x, v[i].x, ss);
            ss = fmaf(v[i].y, v[i].y, ss);
            ss = fmaf(v[i].z, v[i].z, ss);
            ss = fmaf(v[i].w, v[i].w, ss);
        }
    }
    #pragma unroll
    for (int o = 16; o; o >>= 1) ss += __shfl_xor_sync(0xffffffffu, ss, o);
    float inv = 1.0f / fmaxf(sqrtf(ss), 1e-12f);
    #pragma unroll
    for (int i = 0; i < 3; ++i) {
        int f = lane + i * 32;
        if (f < F4N) {
            float4 o4 = make_float4(v[i].x * inv, v[i].y * inv, v[i].z * inv, v[i].w * inv);
            *reinterpret_cast<float4*>(dst + f * 4) = o4;
        }
    }
}

// 2 rows x 20 t, f = ec + 4i over [0, f4cnt); his e-index = (fglob + f)*4 + j
__device__ __forceinline__ void accum_chunk(const float* __restrict__ cbase,
                                            const float* __restrict__ hisT,
                                            int ec, int f4cnt, int fglob,
                                            unsigned long long (&acc)[2][10])
{
    for (int f = ec; f < f4cnt; f += 4) {
        float4 a0 = *reinterpret_cast<const float4*>(cbase + f * 4);
        float4 a1 = *reinterpret_cast<const float4*>(cbase + ROWOFF + f * 4);
        const float* hb = hisT + (fglob + f) * 4 * SS;
        #pragma unroll
        for (int j = 0; j < 4; ++j) {
            float v0 = (j == 0) ? a0.x : (j == 1) ? a0.y : (j == 2) ? a0.z : a0.w;
            float v1 = (j == 0) ? a1.x : (j == 1) ? a1.y : (j == 2) ? a1.z : a1.w;
            unsigned long long d0 = dupf(v0), d1 = dupf(v1);
            const ulonglong2* hp = reinterpret_cast<const ulonglong2*>(hb + j * SS);
            #pragma unroll
            for (int q = 0; q < 5; ++q) {
                ulonglong2 hv = hp[q];
                fma2(acc[0][q * 2 + 0], d0, hv.x);
                fma2(acc[0][q * 2 + 1], d0, hv.y);
                fma2(acc[1][q * 2 + 0], d1, hv.x);
                fma2(acc[1][q * 2 + 1], d1, hv.y);
            }
        }
    }
}

__global__ __launch_bounds__(THREADS, 4)
void knrm_main(const float* __restrict__ cpad, const float* __restrict__ hpad,
               const float* __restrict__ ltr_w, const float* __restrict__ ltr_b,
               float* __restrict__ out)
{
    extern __shared__ float smraw[];
    Smem* sm = reinterpret_cast<Smem*>(smraw);
    const int tid = threadIdx.x;
    const int wid = tid >> 5, lane = tid & 31;
    const int b = blockIdx.x / HH;
    const int h = blockIdx.x % HH;

    const int ec = lane >> 3;
    const int g  = lane & 7;
    const int grp = wid * 8 + g;
    const int grpC = (grp < NGRP2) ? grp : (NGRP2 - 1);

    unsigned long long acc[2][10];
    #pragma unroll
    for (int r = 0; r < 2; ++r)
        #pragma unroll
        for (int p = 0; p < 10; ++p) acc[r][p] = 0ull;

    // -------- preamble: hisT (transposed) + cdd chunk0 + pads --------
    const float* hisSrc = g_hisN + (size_t)(b * HH + h) * SS * EE;
    const float* cddSrc = g_cddN + (size_t)b * NCS * EE;
    for (int i = tid; i < SS * F4N; i += THREADS) {
        int t = i / F4N, f = i % F4N;
        float4 v = *reinterpret_cast<const float4*>(hisSrc + t * EE + f * 4);
        sm->hisT[(f * 4 + 0) * SS + t] = v.x;
        sm->hisT[(f * 4 + 1) * SS + t] = v.y;
        sm->hisT[(f * 4 + 2) * SS + t] = v.z;
        sm->hisT[(f * 4 + 3) * SS + t] = v.w;
    }
    for (int i = tid; i < NCS * 10; i += THREADS) {
        int r = i / 10, f = i % 10;
        float4 v = *reinterpret_cast<const float4*>(cddSrc + r * EE + f * 4);
        *reinterpret_cast<float4*>(sm->cddc + (r >> 1) * GRPSTRIDE + (r & 1) * ROWOFF + f * 4) = v;
    }
    if (tid < SS)  sm->padh[tid] = hpad[(b * HH + h) * SS + tid];
    if (tid < KK)  sm->wv[tid]   = ltr_w[h * KK + tid];
    for (int i = tid; i < NCS; i += THREADS) sm->padc[i] = cpad[b * NCS + i];
    __syncthreads();

    // -------- chunked phase A --------
    #pragma unroll 1
    for (int k = 0; k < NCHUNK; ++k) {
        accum_chunk(sm->cddc + grpC * GRPSTRIDE, sm->hisT, ec, c_f4cnt[k], c_f4off[k], acc);
        __syncthreads();                  // all reads of chunk k done
        if (k + 1 < NCHUNK) {
            int cnt = c_f4cnt[k + 1], off = c_f4off[k + 1];
            for (int i = tid; i < NCS * cnt; i += THREADS) {
                int r = i / cnt, f = i % cnt;
                float4 v = *reinterpret_cast<const float4*>(cddSrc + r * EE + (off + f) * 4);
                *reinterpret_cast<float4*>(sm->cddc + (r >> 1) * GRPSTRIDE + (r & 1) * ROWOFF + f * 4) = v;
            }
            __syncthreads();              // chunk k+1 visible
        }
    }

    // -------- reduce over ec (16, 8 -> lanes 0..7) --------
    #pragma unroll
    for (int o = 16; o >= 8; o >>= 1) {
        #pragma unroll
        for (int r = 0; r < 2; ++r)
            #pragma unroll
            for (int p = 0; p < 10; ++p) {
                unsigned long long other = __shfl_down_sync(0xffffffffu, acc[r][p], o);
                float2 a = *reinterpret_cast<float2*>(&acc[r][p]);
                float2 bo = *reinterpret_cast<float2*>(&other);
                a.x += bo.x; a.y += bo.y;
                acc[r][p] = *reinterpret_cast<unsigned long long*>(&a);
            }
    }
    if (lane < 8 && grp < NGRP2) {
        int r0 = grp * 2;
        #pragma unroll
        for (int r = 0; r < 2; ++r) {
            #pragma unroll
            for (int p = 0; p < 10; ++p) {
                float2 a = *reinterpret_cast<float2*>(&acc[r][p]);
                int t0 = p * 2;
                sm->simbuf[(r0 + r) * SS + t0 + 0] = a.x;
                sm->simbuf[(r0 + r) * SS + t0 + 1] = a.y;
            }
        }
    }
    __syncthreads();

    // -------- phase B --------
    float contrib = 0.0f;
    if (tid < 200) {
        int cs = tid >> 1, kh = tid & 1;
        float ps[10];
        #pragma unroll
        for (int k = 0; k < 10; ++k) ps[k] = 0.f;
        for (int t = 0; t < SS; ++t) {
            float s  = sm->simbuf[cs * SS + t];
            float pt = sm->padh[t];
            #pragma unroll
            for (int k = 0; k < 10; ++k) {
                int kk = kh * 10 + k;
                float mu = -0.9f + 0.1f * (float)kk;
                float nc = (kh == 1 && k == 9) ? NC_LAST : NC_STD;
                float d = s - mu;
                ps[k] = fmaf(pt, ex2_approx(d * d * nc), ps[k]);
            }
        }
        float accw = 0.f;
        #pragma unroll
        for (int k = 0; k < 10; ++k) {
            float lp = __logf(fmaxf(ps[k], 1e-10f));
            accw = fmaf(lp, sm->wv[kh * 10 + k], accw);
        }
        contrib = accw * 0.01f * sm->padc[cs];
    }
    sm->cont[tid] = contrib;
    __syncthreads();

    if (tid < CC) {
        float s = 0.f;
        #pragma unroll 8
        for (int i = 0; i < 40; ++i) s += sm->cont[tid * 40 + i];
        g_partial[(b * HH + h) * CC + tid] = s;
    }
    __syncthreads();

    // -------- fused finalize --------
    __shared__ unsigned int isLast;
    if (tid == 0) {
        __threadfence();
        unsigned int v = atomicAdd(&g_done, 1u);
        isLast = (v == (unsigned)(BB * HH - 1)) ? 1u : 0u;
    }
    __syncthreads();
    if (isLast) {
        if (tid == 0) { g_done = 0; __threadfence(); }
        float* sc = sm->cont;
        if (tid < BB * CC) {
            int bb2 = tid / CC, c = tid % CC;
            float s = ltr_b[0];
            for (int hh = 0; hh < HH; ++hh)
                s += g_partial[(bb2 * HH + hh) * CC + c];
            sc[tid] = s;
        }
        __syncthreads();
        if (tid < BB * CC) {
            int bb2 = tid / CC;
            float m = -1e30f;
            #pragma unroll
            for (int c2 = 0; c2 < CC; ++c2) m = fmaxf(m, sc[bb2 * CC + c2]);
            float se = 0.f;
            #pragma unroll
            for (int c2 = 0; c2 < CC; ++c2) se += expf(sc[bb2 * CC + c2] - m);
            out[tid] = sc[tid] - m - logf(se);
        }
    }
}

extern "C" void kernel_launch(void* const* d_in, const int* in_sizes, int n_in,
                              void* d_out, int out_size)
{
    const int*   cand = (const int*)  d_in[0];
    const int*   clk  = (const int*)  d_in[1];
    const float* cpad = (const float*)d_in[2];
    const float* hpad = (const float*)d_in[3];
    const float* emb  = (const float*)d_in[4];
    const float* w    = (const float*)d_in[5];
    const float* bb   = (const float*)d_in[6];

    size_t smem = sizeof(Smem);
    cudaFuncSetAttribute(knrm_main, cudaFuncAttributeMaxDynamicSharedMemorySize, (int)smem);

    knrm_prep<<<(NROWS_ALL + 7) / 8, 256>>>(cand, clk, emb);
    knrm_main<<<BB * HH, THREADS, smem>>>(cpad, hpad, w, bb, (float*)d_out);
}

// round 11
// speedup vs baseline: 1.2100x; 1.2100x over previous
#include <cuda_runtime.h>
#include <cuda_bf16.h>
#include <cstdint>

#define BB 32
#define CC 5
#define HH 50
#define SS 20
#define EE 300
#define EP 320               // padded E (zeros in 300..319)
#define KK 20
#define F4N 75
#define NCS 100
#define THREADS 224
#define NGRP2 50             // 2-row groups
#define ROWOFF 32            // floats: row1 offset within group (8 float4)
#define GRPSTRIDE 68         // 68 mod 32 = 4 -> staggered banks
#define BUFSZ (NGRP2 * GRPSTRIDE)   // 3400 floats
#define NCHUNK 10
#define CHUNK_F4 8
#define CHUNK_ITEMS (NCS * CHUNK_F4)   // 800
#define NROWS_CDD (BB * CC * SS)     // 3200
#define NROWS_HIS (BB * HH * SS)     // 32000
#define NROWS_ALL (NROWS_CDD + NROWS_HIS)

#define NC_STD  (-72.134752f)
#define NC_LAST (-721347.52f)

struct Smem {
    float hisT[EP * SS];        // 25600B, e-major [e][t], pad e>=300 zeroed
    float cddc[2][BUFSZ];       // 27200B double buffer
    float simbuf[NCS * SS];     // 8000B
    float padh[SS];
    float padc[NCS];
    float wv[KK];
    float cont[THREADS];
};

__device__ float g_cddN[NROWS_CDD * EP];   // normalized + zero-padded to EP
__device__ float g_hisN[NROWS_HIS * EE];
__device__ float g_partial[BB * HH * CC];
__device__ unsigned int g_done;

__device__ __forceinline__ float ex2_approx(float x) {
    float r;
    asm("ex2.approx.ftz.f32 %0, %1;" : "=f"(r) : "f"(x));
    return r;
}
__device__ __forceinline__ void fma2(unsigned long long& acc,
                                     unsigned long long a, unsigned long long b) {
    asm("fma.rn.f32x2 %0, %1, %2, %0;" : "+l"(acc) : "l"(a), "l"(b));
}
__device__ __forceinline__ unsigned long long dupf(float x) {
    unsigned long long r;
    asm("mov.b64 %0, {%1, %1};" : "=l"(r) : "f"(x));
    return r;
}

// ---------------- prep: L2-normalize embedding rows into dense scratch ----------------
__global__ __launch_bounds__(256)
void knrm_prep(const int* __restrict__ cand, const int* __restrict__ clk,
               const float* __restrict__ emb)
{
    const int wid = threadIdx.x >> 5, lane = threadIdx.x & 31;
    const int row = blockIdx.x * 8 + wid;
    if (row >= NROWS_ALL) return;
    const bool isCdd = (row < NROWS_CDD);
    int tok;
    float* dst;
    if (isCdd) { tok = cand[row];             dst = g_cddN + (size_t)row * EP; }
    else       { tok = clk[row - NROWS_CDD];  dst = g_hisN + (size_t)(row - NROWS_CDD) * EE; }
    const float* src = emb + (size_t)tok * EE;

    float4 v[3];
    float ss = 0.f;
    #pragma unroll
    for (int i = 0; i < 3; ++i) {
        int f = lane + i * 32;
        if (f < F4N) {
            v[i] = *reinterpret_cast<const float4*>(src + f * 4);
            ss = fmaf(v[i].x, v[i].x, ss);
            ss = fmaf(v[i].y, v[i].y, ss);
            ss = fmaf(v[i].z, v[i].z, ss);
            ss = fmaf(v[i].w, v[i].w, ss);
        }
    }
    #pragma unroll
    for (int o = 16; o; o >>= 1) ss += __shfl_xor_sync(0xffffffffu, ss, o);
    float inv = 1.0f / fmaxf(sqrtf(ss), 1e-12f);
    #pragma unroll
    for (int i = 0; i < 3; ++i) {
        int f = lane + i * 32;
        if (f < F4N) {
            float4 o4 = make_float4(v[i].x * inv, v[i].y * inv, v[i].z * inv, v[i].w * inv);
            *reinterpret_cast<float4*>(dst + f * 4) = o4;
        } else if (isCdd && f < EP / 4) {
            *reinterpret_cast<float4*>(dst + f * 4) = make_float4(0.f, 0.f, 0.f, 0.f);
        }
    }
}

// 2 rows x 20 t over 8 float4 (f = ec, ec+4); hb0 = hisT chunk base
__device__ __forceinline__ void accum_chunk(const float* __restrict__ cbase,
                                            const float* __restrict__ hb0,
                                            int ec,
                                            unsigned long long (&acc)[2][10])
{
    #pragma unroll
    for (int i = 0; i < 2; ++i) {
        int f = ec + 4 * i;
        float4 a0 = *reinterpret_cast<const float4*>(cbase + f * 4);
        float4 a1 = *reinterpret_cast<const float4*>(cbase + ROWOFF + f * 4);
        const float* hb = hb0 + f * 4 * SS;
        #pragma unroll
        for (int j = 0; j < 4; ++j) {
            float v0 = (j == 0) ? a0.x : (j == 1) ? a0.y : (j == 2) ? a0.z : a0.w;
            float v1 = (j == 0) ? a1.x : (j == 1) ? a1.y : (j == 2) ? a1.z : a1.w;
            unsigned long long d0 = dupf(v0), d1 = dupf(v1);
            const ulonglong2* hp = reinterpret_cast<const ulonglong2*>(hb + j * SS);
            #pragma unroll
            for (int q = 0; q < 5; ++q) {
                ulonglong2 hv = hp[q];
                fma2(acc[0][q * 2 + 0], d0, hv.x);
                fma2(acc[0][q * 2 + 1], d0, hv.y);
                fma2(acc[1][q * 2 + 0], d1, hv.x);
                fma2(acc[1][q * 2 + 1], d1, hv.y);
            }
        }
    }
}

__global__ __launch_bounds__(THREADS, 3)
void knrm_main(const float* __restrict__ cpad, const float* __restrict__ hpad,
               const float* __restrict__ ltr_w, const float* __restrict__ ltr_b,
               float* __restrict__ out)
{
    extern __shared__ float smraw[];
    Smem* sm = reinterpret_cast<Smem*>(smraw);
    const int tid = threadIdx.x;
    const int wid = tid >> 5, lane = tid & 31;
    const int b = blockIdx.x / HH;
    const int h = blockIdx.x % HH;

    const int ec = lane >> 3;
    const int g  = lane & 7;
    const int grp = wid * 8 + g;
    const int grpC = (grp < NGRP2) ? grp : (NGRP2 - 1);

    unsigned long long acc[2][10];
    #pragma unroll
    for (int r = 0; r < 2; ++r)
        #pragma unroll
        for (int p = 0; p < 10; ++p) acc[r][p] = 0ull;

    const float* hisSrc = g_hisN + (size_t)(b * HH + h) * SS * EE;
    const float* cddSrc = g_cddN + (size_t)b * NCS * EP;

    // precomputed chunk-load slots (same pattern every chunk)
    int srcOff[4], dstOff[4];
    bool sval[4];
    #pragma unroll
    for (int s = 0; s < 4; ++s) {
        int idx = tid + s * THREADS;
        sval[s] = (idx < CHUNK_ITEMS);
        int r = idx >> 3, f = idx & 7;
        srcOff[s] = r * EP + f * 4;
        dstOff[s] = (r >> 1) * GRPSTRIDE + (r & 1) * ROWOFF + f * 4;
    }

    // -------- preamble: hisT (transposed) + zero pad + chunk0 + pads --------
    for (int i = tid; i < SS * F4N; i += THREADS) {
        int t = i / F4N, f = i % F4N;
        float4 v = *reinterpret_cast<const float4*>(hisSrc + t * EE + f * 4);
        sm->hisT[(f * 4 + 0) * SS + t] = v.x;
        sm->hisT[(f * 4 + 1) * SS + t] = v.y;
        sm->hisT[(f * 4 + 2) * SS + t] = v.z;
        sm->hisT[(f * 4 + 3) * SS + t] = v.w;
    }
    for (int i = tid; i < (EP - EE) * SS; i += THREADS)
        sm->hisT[EE * SS + i] = 0.f;
    #pragma unroll
    for (int s = 0; s < 4; ++s)
        if (sval[s])
            *reinterpret_cast<float4*>(&sm->cddc[0][dstOff[s]]) =
                *reinterpret_cast<const float4*>(cddSrc + srcOff[s]);
    if (tid < SS)  sm->padh[tid] = hpad[(b * HH + h) * SS + tid];
    if (tid < KK)  sm->wv[tid]   = ltr_w[h * KK + tid];
    for (int i = tid; i < NCS; i += THREADS) sm->padc[i] = cpad[b * NCS + i];
    __syncthreads();

    // -------- double-buffered phase A: 10 chunks, 1 barrier each --------
    #pragma unroll
    for (int k = 0; k < NCHUNK; ++k) {
        if (k + 1 < NCHUNK) {
            const float* src = cddSrc + (k + 1) * (CHUNK_F4 * 4);
            float* dbuf = sm->cddc[(k + 1) & 1];
            #pragma unroll
            for (int s = 0; s < 4; ++s)
                if (sval[s])
                    *reinterpret_cast<float4*>(&dbuf[dstOff[s]]) =
                        *reinterpret_cast<const float4*>(src + srcOff[s]);
        }
        accum_chunk(sm->cddc[k & 1] + grpC * GRPSTRIDE,
                    sm->hisT + k * (CHUNK_F4 * 4) * SS, ec, acc);
        __syncthreads();
    }

    // -------- reduce over ec (16, 8 -> lanes 0..7) --------
    #pragma unroll
    for (int o = 16; o >= 8; o >>= 1) {
        #pragma unroll
        for (int r = 0; r < 2; ++r)
            #pragma unroll
            for (int p = 0; p < 10; ++p) {
                unsigned long long other = __shfl_down_sync(0xffffffffu, acc[r][p], o);
                float2 a = *reinterpret_cast<float2*>(&acc[r][p]);
                float2 bo = *reinterpret_cast<float2*>(&other);
                a.x += bo.x; a.y += bo.y;
                acc[r][p] = *reinterpret_cast<unsigned long long*>(&a);
            }
    }
    if (lane < 8 && grp < NGRP2) {
        int r0 = grp * 2;
        #pragma unroll
        for (int r = 0; r < 2; ++r) {
            #pragma unroll
            for (int p = 0; p < 10; ++p) {
                float2 a = *reinterpret_cast<float2*>(&acc[r][p]);
                int t0 = p * 2;
                sm->simbuf[(r0 + r) * SS + t0 + 0] = a.x;
                sm->simbuf[(r0 + r) * SS + t0 + 1] = a.y;
            }
        }
    }
    __syncthreads();

    // -------- phase B --------
    float contrib = 0.0f;
    if (tid < 200) {
        int cs = tid >> 1, kh = tid & 1;
        float ps[10];
        #pragma unroll
        for (int k = 0; k < 10; ++k) ps[k] = 0.f;
        for (int t = 0; t < SS; ++t) {
            float s  = sm->simbuf[cs * SS + t];
            float pt = sm->padh[t];
            #pragma unroll
            for (int k = 0; k < 10; ++k) {
                int kk = kh * 10 + k;
                float mu = -0.9f + 0.1f * (float)kk;
                float nc = (kh == 1 && k == 9) ? NC_LAST : NC_STD;
                float d = s - mu;
                ps[k] = fmaf(pt, ex2_approx(d * d * nc), ps[k]);
            }
        }
        float accw = 0.f;
        #pragma unroll
        for (int k = 0; k < 10; ++k) {
            float lp = __logf(fmaxf(ps[k], 1e-10f));
            accw = fmaf(lp, sm->wv[kh * 10 + k], accw);
        }
        contrib = accw * 0.01f * sm->padc[cs];
    }
    sm->cont[tid] = contrib;
    __syncthreads();

    if (tid < CC) {
        float s = 0.f;
        #pragma unroll 8
        for (int i = 0; i < 40; ++i) s += sm->cont[tid * 40 + i];
        g_partial[(b * HH + h) * CC + tid] = s;
    }
    __syncthreads();

    // -------- fused finalize --------
    __shared__ unsigned int isLast;
    if (tid == 0) {
        __threadfence();
        unsigned int v = atomicAdd(&g_done, 1u);
        isLast = (v == (unsigned)(BB * HH - 1)) ? 1u : 0u;
    }
    __syncthreads();
    if (isLast) {
        if (tid == 0) { g_done = 0; __threadfence(); }
        float* sc = sm->cont;
        if (tid < BB * CC) {
            int bb2 = tid / CC, c = tid % CC;
            float s = ltr_b[0];
            for (int hh = 0; hh < HH; ++hh)
                s += g_partial[(bb2 * HH + hh) * CC + c];
            sc[tid] = s;
        }
        __syncthreads();
        if (tid < BB * CC) {
            int bb2 = tid / CC;
            float m = -1e30f;
            #pragma unroll
            for (int c2 = 0; c2 < CC; ++c2) m = fmaxf(m, sc[bb2 * CC + c2]);
            float se = 0.f;
            #pragma unroll
            for (int c2 = 0; c2 < CC; ++c2) se += expf(sc[bb2 * CC + c2] - m);
            out[tid] = sc[tid] - m - logf(se);
        }
    }
}

extern "C" void kernel_launch(void* const* d_in, const int* in_sizes, int n_in,
                              void* d_out, int out_size)
{
    const int*   cand = (const int*)  d_in[0];
    const int*   clk  = (const int*)  d_in[1];
    const float* cpad = (const float*)d_in[2];
    const float* hpad = (const float*)d_in[3];
    const float* emb  = (const float*)d_in[4];
    const float* w    = (const float*)d_in[5];
    const float* bb   = (const float*)d_in[6];

    size_t smem = sizeof(Smem);
    cudaFuncSetAttribute(knrm_main, cudaFuncAttributeMaxDynamicSharedMemorySize, (int)smem);

    knrm_prep<<<(NROWS_ALL + 7) / 8, 256>>>(cand, clk, emb);
    knrm_main<<<BB * HH, THREADS, smem>>>(cpad, hpad, w, bb, (float*)d_out);
}